// round 4
// baseline (speedup 1.0000x reference)
#include <cuda_runtime.h>
#include <math.h>
#include <stddef.h>

// Problem constants
#define BATCH 4
#define HH 48
#define WW 48
#define DD 64
#define HC 46                 // valid patch grid
#define CC 2116               // HC*HC candidate patches
#define MM 2304               // HH*WW locations
#define TEMPR 50.0f

// Scratch (device globals -- no runtime allocation allowed)
static __device__ float g_E [(size_t)BATCH * MM * MM];   // E Gram (85 MB)
static __device__ float g_DS[(size_t)BATCH * MM * CC];   // CA (78 MB)
static __device__ float g_bg [BATCH * MM * DD];          // g_in * mask
static __device__ float g_sg [BATCH * MM];               // per-pixel sum g^2
static __device__ float g_sbg[BATCH * MM];               // per-pixel sum bg^2
static __device__ float g_wwd[BATCH * MM];               // 3x3 box sum (same pad) of g_sg
static __device__ float g_k1d[BATCH * CC];               // 3x3 box sum (valid) of g_sbg
static __device__ float g_ACL[BATCH * MM * DD];

// ---------------------------------------------------------------------------
// Kernel 0a: bg = g_in * mask ; per-pixel sums of squares
__global__ void prep_kernel(const float* __restrict__ gin, const float* __restrict__ mask) {
    int p = blockIdx.x;
    int d = threadIdx.x;
    float mv = mask[p];
    float g  = gin[p * DD + d];
    float bgv = g * mv;
    g_bg[p * DD + d] = bgv;
    __shared__ float s1[DD];
    __shared__ float s2[DD];
    s1[d] = g * g;
    s2[d] = bgv * bgv;
    __syncthreads();
    #pragma unroll
    for (int s = 32; s > 0; s >>= 1) {
        if (d < s) { s1[d] += s1[d + s]; s2[d] += s2[d + s]; }
        __syncthreads();
    }
    if (d == 0) { g_sg[p] = s1[0]; g_sbg[p] = s2[0]; }
}

// Kernel 0b: box sums -> wwd (same pad) and k1d (valid)
__global__ void boxsum_kernel() {
    int idx = blockIdx.x * blockDim.x + threadIdx.x;
    if (idx < BATCH * MM) {
        int b = idx / MM, m = idx - b * MM;
        int y = m / WW, x = m - y * WW;
        float s = 0.f;
        #pragma unroll
        for (int dy = 0; dy < 3; dy++)
            #pragma unroll
            for (int dx = 0; dx < 3; dx++) {
                int yy = y + dy - 1, xx = x + dx - 1;
                if (yy >= 0 && yy < HH && xx >= 0 && xx < WW)
                    s += g_sg[(b * HH + yy) * WW + xx];
            }
        g_wwd[idx] = s;
    } else if (idx < BATCH * MM + BATCH * CC) {
        int id2 = idx - BATCH * MM;
        int b = id2 / CC, j = id2 - b * CC;
        int jy = j / HC, jx = j - jy * HC;
        float s = 0.f;
        #pragma unroll
        for (int dy = 0; dy < 3; dy++)
            #pragma unroll
            for (int dx = 0; dx < 3; dx++)
                s += g_sbg[(b * HH + jy + dy) * WW + jx + dx];
        g_k1d[id2] = s;
    }
}

// ---------------------------------------------------------------------------
// gemmE: E[b,p,q] = sum_ch gin[b,p,ch] * bg[b,q,ch].  M=N=2304, K=64.
__global__ __launch_bounds__(256) void gemmE_kernel(const float* __restrict__ gin) {
    __shared__ float As[16][64];
    __shared__ float Bs[16][64];
    int b  = blockIdx.z;
    int p0 = blockIdx.y * 64;
    int q0 = blockIdx.x * 64;
    int tid = threadIdx.x;
    int lk = (tid & 3) * 4;
    int lr = tid >> 2;
    int ty = tid >> 4, tx = tid & 15;

    const float* A = gin  + (size_t)b * MM * DD;
    const float* B = g_bg + (size_t)b * MM * DD;

    float acc[4][4];
    #pragma unroll
    for (int i = 0; i < 4; i++)
        #pragma unroll
        for (int j = 0; j < 4; j++) acc[i][j] = 0.f;

    #pragma unroll
    for (int k0 = 0; k0 < DD; k0 += 16) {
        float4 va = *(const float4*)(A + (p0 + lr) * DD + k0 + lk);
        As[lk + 0][lr] = va.x; As[lk + 1][lr] = va.y;
        As[lk + 2][lr] = va.z; As[lk + 3][lr] = va.w;
        float4 vb = *(const float4*)(B + (q0 + lr) * DD + k0 + lk);
        Bs[lk + 0][lr] = vb.x; Bs[lk + 1][lr] = vb.y;
        Bs[lk + 2][lr] = vb.z; Bs[lk + 3][lr] = vb.w;
        __syncthreads();
        #pragma unroll
        for (int k = 0; k < 16; k++) {
            float4 a4 = *(const float4*)(&As[k][ty * 4]);
            float4 b4 = *(const float4*)(&Bs[k][tx * 4]);
            float av[4] = {a4.x, a4.y, a4.z, a4.w};
            float bv[4] = {b4.x, b4.y, b4.z, b4.w};
            #pragma unroll
            for (int i = 0; i < 4; i++)
                #pragma unroll
                for (int j = 0; j < 4; j++) acc[i][j] += av[i] * bv[j];
        }
        __syncthreads();
    }

    float* Eb = g_E + (size_t)b * MM * MM;
    #pragma unroll
    for (int i = 0; i < 4; i++) {
        float4 v;
        v.x = acc[i][0]; v.y = acc[i][1]; v.z = acc[i][2]; v.w = acc[i][3];
        *(float4*)(Eb + (size_t)(p0 + ty * 4 + i) * MM + q0 + tx * 4) = v;
    }
}

// ---------------------------------------------------------------------------
// Block-wide dual sum over 256 threads via shuffle + 16-slot smem.
__device__ __forceinline__ void block_sum256x2(float& a, float& b, float* red) {
    int tid = threadIdx.x;
    #pragma unroll
    for (int o = 16; o > 0; o >>= 1) {
        a += __shfl_xor_sync(0xffffffffu, a, o);
        b += __shfl_xor_sync(0xffffffffu, b, o);
    }
    __syncthreads();
    if ((tid & 31) == 0) { red[tid >> 5] = a; red[8 + (tid >> 5)] = b; }
    __syncthreads();
    a = red[0] + red[1] + red[2] + red[3] + red[4] + red[5] + red[6] + red[7];
    b = red[8] + red[9] + red[10] + red[11] + red[12] + red[13] + red[14] + red[15];
}

// ---------------------------------------------------------------------------
// Fused DS + tanh-normalized softmax.  One CTA per PAIR of rows (x, x+1):
// taps of the two rows hit adjacent addresses -> L1/L2 line reuse.
__global__ __launch_bounds__(256) void ds_softmax_kernel() {
    __shared__ float red[16];
    int pair = blockIdx.x;
    int b = pair / (MM / 2);
    int mp = pair - b * (MM / 2);
    int m0 = mp * 2;
    int y = m0 / WW, x0 = m0 - y * WW;   // x0 even, same y for both
    int tid = threadIdx.x;

    const float* Eb = g_E + (size_t)b * MM * MM;
    const float* base0 = Eb + (ptrdiff_t)((y - 1) * WW + (x0 - 1)) * MM;
    const float* base1 = base0 + MM;
    float wv0 = g_wwd[b * MM + m0];
    float wv1 = g_wwd[b * MM + m0 + 1];
    const float* k1 = g_k1d + b * CC;

    bool tvy[3], tvx0[3], tvx1[3];
    #pragma unroll
    for (int t = 0; t < 3; t++) {
        tvy[t]  = (unsigned)(y + t - 1)  < (unsigned)HH;
        tvx0[t] = (unsigned)(x0 + t - 1) < (unsigned)WW;
        tvx1[t] = (unsigned)(x0 + t)     < (unsigned)WW;
    }
    bool interior = tvy[0] && tvy[2] && tvx0[0] && tvx1[2];

    float v0[9], v1[9];
    float s0 = 0.f, s1 = 0.f;

    if (interior) {
        #pragma unroll
        for (int i = 0; i < 9; i++) {
            int n = tid + 256 * i;
            if (n < CC) {
                int jy = n / HC, jx = n - jy * HC;
                const float* p0 = base0 + (jy * WW + jx);
                const float* p1 = base1 + (jy * WW + jx);
                float cs0 = 0.f, cs1 = 0.f;
                #pragma unroll
                for (int dy = 0; dy < 3; dy++)
                    #pragma unroll
                    for (int dx = 0; dx < 3; dx++) {
                        int off = (dy * WW + dx) * (MM + 1);
                        cs0 += p0[off];
                        cs1 += p1[off];
                    }
                float a0 = fmaf(-2.f, cs0, k1[n] + wv0);
                float a1 = fmaf(-2.f, cs1, k1[n] + wv1);
                v0[i] = a0; v1[i] = a1;
                s0 += a0; s1 += a1;
            } else { v0[i] = 0.f; v1[i] = 0.f; }
        }
    } else {
        #pragma unroll
        for (int i = 0; i < 9; i++) {
            int n = tid + 256 * i;
            if (n < CC) {
                int jy = n / HC, jx = n - jy * HC;
                const float* p0 = base0 + (jy * WW + jx);
                const float* p1 = base1 + (jy * WW + jx);
                float cs0 = 0.f, cs1 = 0.f;
                #pragma unroll
                for (int dy = 0; dy < 3; dy++)
                    #pragma unroll
                    for (int dx = 0; dx < 3; dx++) {
                        int off = (dy * WW + dx) * (MM + 1);
                        if (tvy[dy] && tvx0[dx]) cs0 += p0[off];
                        if (tvy[dy] && tvx1[dx]) cs1 += p1[off];
                    }
                float a0 = fmaf(-2.f, cs0, k1[n] + wv0);
                float a1 = fmaf(-2.f, cs1, k1[n] + wv1);
                v0[i] = a0; v1[i] = a1;
                s0 += a0; s1 += a1;
            } else { v0[i] = 0.f; v1[i] = 0.f; }
        }
    }

    block_sum256x2(s0, s1, red);
    float mu0 = s0 * (1.0f / CC), mu1 = s1 * (1.0f / CC);

    float q0 = 0.f, q1 = 0.f;
    #pragma unroll
    for (int i = 0; i < 9; i++) {
        int n = tid + 256 * i;
        if (n < CC) {
            float d0 = v0[i] - mu0; q0 = fmaf(d0, d0, q0);
            float d1 = v1[i] - mu1; q1 = fmaf(d1, d1, q1);
        }
    }
    block_sum256x2(q0, q1, red);
    float isd0 = rsqrtf(q0 * (1.0f / CC));
    float isd1 = rsqrtf(q1 * (1.0f / CC));

    // e = exp(-TEMP*tanh(w)) = exp(100/(e^{2w}+1) - 50)
    float se0 = 0.f, se1 = 0.f;
    #pragma unroll
    for (int i = 0; i < 9; i++) {
        int n = tid + 256 * i;
        if (n < CC) {
            float w0 = (v0[i] - mu0) * isd0;
            float u0 = __expf(2.f * w0);
            float e0 = __expf(__fdividef(100.f, u0 + 1.f) - 50.f);
            v0[i] = e0; se0 += e0;
            float w1 = (v1[i] - mu1) * isd1;
            float u1 = __expf(2.f * w1);
            float e1 = __expf(__fdividef(100.f, u1 + 1.f) - 50.f);
            v1[i] = e1; se1 += e1;
        }
    }
    block_sum256x2(se0, se1, red);
    float inv0 = 1.0f / se0, inv1 = 1.0f / se1;

    float* rp0 = g_DS + (size_t)(b * MM + m0) * CC;
    float* rp1 = rp0 + CC;
    #pragma unroll
    for (int i = 0; i < 9; i++) {
        int n = tid + 256 * i;
        if (n < CC) { rp0[n] = v0[i] * inv0; rp1[n] = v1[i] * inv1; }
    }
}

// ---------------------------------------------------------------------------
// Fused S-gather + GEMM:
//   acl[m,d] = sum_q S[m,q]*bg[q,d],  S[m,q] = sum_t CA[row_t(m), col_t(q)]
// A-loader computes the 9-tap sums on the fly; lanes map to q (contiguous CA
// columns) and transpose through padded smem.  BM=32, BN=64, BK=32.
// Epilogue: ACL = bg + acl/9*(1-mask).
__global__ __launch_bounds__(256) void acl_fused_kernel(const float* __restrict__ mask) {
    __shared__ float As[32][33];   // As[k][m], padded
    __shared__ float Bs[32][64];
    int b  = blockIdx.y;
    int m0 = blockIdx.x * 32;
    int tid = threadIdx.x;
    int w = tid >> 5, l = tid & 31;
    int ty = tid >> 4, tx = tid & 15;

    const float* CAb = g_DS + (size_t)b * MM * CC;
    const float* bgb = g_bg + (size_t)b * MM * DD;

    // per m-instance (m = m0 + w + 8*i) row base + m-side tap validity mask
    int mrow[4];
    unsigned predm[4];
    #pragma unroll
    for (int i = 0; i < 4; i++) {
        int mi = m0 + w + 8 * i;
        int yy = mi / WW, xx = mi - yy * WW;
        mrow[i] = ((yy + 1) * WW + (xx + 1)) * CC;
        unsigned pm = 0;
        #pragma unroll
        for (int dy = 0; dy < 3; dy++)
            #pragma unroll
            for (int dx = 0; dx < 3; dx++)
                if ((unsigned)(yy + 1 - dy) < (unsigned)HH &&
                    (unsigned)(xx + 1 - dx) < (unsigned)WW)
                    pm |= 1u << (dy * 3 + dx);
        predm[i] = pm;
    }

    float acc[2][4];
    #pragma unroll
    for (int i = 0; i < 2; i++)
        #pragma unroll
        for (int j = 0; j < 4; j++) acc[i][j] = 0.f;

    for (int k0 = 0; k0 < MM; k0 += 32) {
        // ---- A loader: lane l handles q = k0 + l ----
        int q = k0 + l;
        int qy = q / WW, qx = q - qy * WW;
        int colb = qy * HC + qx;
        unsigned predq = 0;
        #pragma unroll
        for (int dy = 0; dy < 3; dy++)
            #pragma unroll
            for (int dx = 0; dx < 3; dx++)
                if ((unsigned)(qy - dy) < (unsigned)HC &&
                    (unsigned)(qx - dx) < (unsigned)HC)
                    predq |= 1u << (dy * 3 + dx);
        #pragma unroll
        for (int i = 0; i < 4; i++) {
            const float* p = CAb + mrow[i] + colb;
            unsigned pr = predm[i] & predq;
            float s = 0.f;
            #pragma unroll
            for (int dy = 0; dy < 3; dy++)
                #pragma unroll
                for (int dx = 0; dx < 3; dx++)
                    if (pr & (1u << (dy * 3 + dx)))
                        s += p[-((dy * WW + dx) * CC + dy * HC + dx)];
            As[l][w + 8 * i] = s;
        }
        // ---- B loader ----
        {
            float4 vb = *(const float4*)(bgb + (k0 + ty) * DD + tx * 4);
            *(float4*)(&Bs[ty][tx * 4]) = vb;
            float4 vb2 = *(const float4*)(bgb + (k0 + ty + 16) * DD + tx * 4);
            *(float4*)(&Bs[ty + 16][tx * 4]) = vb2;
        }
        __syncthreads();
        #pragma unroll
        for (int k = 0; k < 32; k++) {
            float a0 = As[k][ty * 2 + 0];
            float a1 = As[k][ty * 2 + 1];
            float4 b4 = *(const float4*)(&Bs[k][tx * 4]);
            acc[0][0] += a0 * b4.x; acc[0][1] += a0 * b4.y;
            acc[0][2] += a0 * b4.z; acc[0][3] += a0 * b4.w;
            acc[1][0] += a1 * b4.x; acc[1][1] += a1 * b4.y;
            acc[1][2] += a1 * b4.z; acc[1][3] += a1 * b4.w;
        }
        __syncthreads();
    }

    #pragma unroll
    for (int i = 0; i < 2; i++) {
        int rowm = b * MM + m0 + ty * 2 + i;
        float om = (1.f - mask[rowm]) * (1.f / 9.f);
        #pragma unroll
        for (int j = 0; j < 4; j++) {
            int idx = rowm * DD + tx * 4 + j;
            g_ACL[idx] = g_bg[idx] + acc[i][j] * om;
        }
    }
}

// ---------------------------------------------------------------------------
// Final: out = elu(concat(g_in, ACL) @ W2 + b2).  4 rows x 64 cols per block.
__global__ __launch_bounds__(256) void final_kernel(const float* __restrict__ gin,
                                                    const float* __restrict__ W2,
                                                    const float* __restrict__ b2,
                                                    float* __restrict__ out) {
    __shared__ float sA[4][128];
    int r0 = blockIdx.x * 4;
    int tid = threadIdx.x;
    for (int idx = tid; idx < 512; idx += 256) {
        int r = idx >> 7, k = idx & 127;
        int row = r0 + r;
        sA[r][k] = (k < DD) ? gin[row * DD + k] : g_ACL[row * DD + (k - DD)];
    }
    __syncthreads();
    int r = tid >> 6, d = tid & 63;
    int row = r0 + r;
    float acc = b2[d];
    #pragma unroll 8
    for (int k = 0; k < 128; k++) acc += sA[r][k] * W2[k * DD + d];
    out[row * DD + d] = (acc > 0.f) ? acc : expm1f(acc);
}

// ---------------------------------------------------------------------------
extern "C" void kernel_launch(void* const* d_in, const int* in_sizes, int n_in,
                              void* d_out, int out_size) {
    const float* gin  = (const float*)d_in[0];
    const float* mask = (const float*)d_in[1];
    const float* W2   = (const float*)d_in[2];
    const float* b2   = (const float*)d_in[3];
    float* out = (float*)d_out;

    prep_kernel<<<BATCH * MM, DD>>>(gin, mask);
    int tot = BATCH * MM + BATCH * CC;
    boxsum_kernel<<<(tot + 255) / 256, 256>>>();
    gemmE_kernel<<<dim3(MM / 64, MM / 64, BATCH), 256>>>(gin);
    ds_softmax_kernel<<<BATCH * MM / 2, 256>>>();
    acl_fused_kernel<<<dim3(MM / 32, BATCH), 256>>>(mask);
    final_kernel<<<BATCH * MM / 4, 256>>>(gin, W2, b2, out);
}